// round 13
// baseline (speedup 1.0000x reference)
#include <cuda_runtime.h>
#include <cuda_fp16.h>
#include <math.h>
#include <stdint.h>

#define B_  32
#define S_  2048
#define H_  1024
#define BS_ (B_ * S_)

// ---------------- scratch (small device globals only) -----------------------
__device__ __align__(1024) float g_scores[BS_];      // [B,S] logits
__device__ __align__(1024) float g_bias2[B_ * H_];   // [B,H]
__device__ __align__(1024) __half g_W16[H_ * H_];    // W fp16 plane (2 MB)

// =================== PTX helpers ============================================
__device__ __forceinline__ uint32_t smem_u32(const void* p) {
    uint32_t a;
    asm("{ .reg .u64 t; cvta.to.shared.u64 t, %1; cvt.u32.u64 %0, t; }"
        : "=r"(a) : "l"(p));
    return a;
}
__device__ __forceinline__ void ldsm4(uint32_t r[4], uint32_t addr) {
    asm volatile("ldmatrix.sync.aligned.m8n8.x4.shared.b16 {%0,%1,%2,%3}, [%4];"
                 : "=r"(r[0]), "=r"(r[1]), "=r"(r[2]), "=r"(r[3]) : "r"(addr));
}
__device__ __forceinline__ void mma16816(float c[4], const uint32_t a[4],
                                         uint32_t b0, uint32_t b1) {
    asm volatile(
        "mma.sync.aligned.m16n8k16.row.col.f32.f16.f16.f32 "
        "{%0,%1,%2,%3}, {%4,%5,%6,%7}, {%8,%9}, {%0,%1,%2,%3};"
        : "+f"(c[0]), "+f"(c[1]), "+f"(c[2]), "+f"(c[3])
        : "r"(a[0]), "r"(a[1]), "r"(a[2]), "r"(a[3]), "r"(b0), "r"(b1));
}
__device__ __forceinline__ void cp_async16(uint32_t dst, const void* src) {
    asm volatile("cp.async.cg.shared.global [%0], [%1], 16;"
                 :: "r"(dst), "l"(src) : "memory");
}
__device__ __forceinline__ void cp_commit() {
    asm volatile("cp.async.commit_group;" ::: "memory");
}
__device__ __forceinline__ void cp_wait0() {
    asm volatile("cp.async.wait_group 0;" ::: "memory");
}

// fp16 rn split of one float4: xh = rn_f16(x), xl = rn_f16(x - xh).
// dst_hi = hi-plane location; lo plane is +8192 bytes.
__device__ __forceinline__ void split_store_f16(const float4 val, char* dst_hi) {
    const __half h0 = __float2half_rn(val.x);
    const __half h1 = __float2half_rn(val.y);
    const __half h2 = __float2half_rn(val.z);
    const __half h3 = __float2half_rn(val.w);
    __half2 hw0 = __halves2half2(h0, h1);
    __half2 hw1 = __halves2half2(h2, h3);
    const __half l0 = __float2half_rn(val.x - __half2float(h0));
    const __half l1 = __float2half_rn(val.y - __half2float(h1));
    const __half l2 = __float2half_rn(val.z - __half2float(h2));
    const __half l3 = __float2half_rn(val.w - __half2float(h3));
    __half2 lw0 = __halves2half2(l0, l1);
    __half2 lw1 = __halves2half2(l2, l3);
    ((__half2*)dst_hi)[0] = hw0;
    ((__half2*)dst_hi)[1] = hw1;
    ((__half2*)(dst_hi + 8192))[0] = lw0;
    ((__half2*)(dst_hi + 8192))[1] = lw1;
}

// ---------------- SMEM layout for energy_mma --------------------------------
// bias 0..512 | v 512..1024 | fp16 double buffer @1024: 2 x 24KB
// buf layout: AH 0 | AL 8192 | BH 16384 (128 rows x 64B, 16B-chunk swizzled)
#define SM_BIAS   0
#define SM_V      512
#define SM_BF     1024
#define BF_BUF    24576
#define BF_BH     16384
#define SM_TOTAL  (SM_BF + 2 * BF_BUF)    // 50176 -> 2 CTAs/SM (reg-capped)

// ---------------- kernel 0: zero scores + context region --------------------
__global__ void zero_kernel(float* __restrict__ ctx) {
    int i = blockIdx.x * blockDim.x + threadIdx.x;
    if (i < BS_)      g_scores[i] = 0.0f;
    if (i < B_ * H_)  ctx[i]      = 0.0f;
}

// ---------------- kernel 0b: W -> fp16 plane (once per call) ----------------
__global__ void w16_kernel(const float* __restrict__ W) {
    const int i = blockIdx.x * blockDim.x + threadIdx.x;   // one float4 each
    float4 x = ((const float4*)W)[i];
    __half2 a = __halves2half2(__float2half_rn(x.x), __float2half_rn(x.y));
    __half2 b = __halves2half2(__float2half_rn(x.z), __float2half_rn(x.w));
    ((__half2*)g_W16)[2 * i]     = a;
    ((__half2*)g_W16)[2 * i + 1] = b;
}

// ---------------- kernel 1: bias2 = hidden @ W^T + b_attn -------------------
__global__ void bias2_kernel(const float* __restrict__ hidden,
                             const float* __restrict__ W,
                             const float* __restrict__ b_attn) {
    __shared__ float sh[H_];
    const int w    = threadIdx.x >> 5;
    const int lane = threadIdx.x & 31;
    const int o    = blockIdx.x * 8 + w;

    float4 wr[8];
    const float4* wrow = (const float4*)(W + (size_t)o * H_);
#pragma unroll
    for (int i = 0; i < 8; ++i) wr[i] = wrow[lane + i * 32];
    const float ba = b_attn[o];

    for (int b = 0; b < B_; ++b) {
        __syncthreads();
#pragma unroll
        for (int i = threadIdx.x; i < H_; i += 256) sh[i] = hidden[b * H_ + i];
        __syncthreads();

        float sum = 0.0f;
#pragma unroll
        for (int i = 0; i < 8; ++i) {
            float4 h = *(const float4*)(sh + (lane + i * 32) * 4);
            sum += wr[i].x * h.x + wr[i].y * h.y + wr[i].z * h.z + wr[i].w * h.w;
        }
#pragma unroll
        for (int off = 16; off; off >>= 1)
            sum += __shfl_xor_sync(0xffffffffu, sum, off);
        if (lane == 0) g_bias2[b * H_ + o] = sum + ba;
    }
}

// ---------------- kernel 2: fp16 2-product split GEMM + tanh + dot(v) -------
// scores[b,s] += sum_o v[o]*tanh(enc[s]·W[o] + bias2[b,o])
// x*w ~ xh*wh + xl*wh. Warp tile 32x64 (4M x 2N) -> ldsm 8/warp/k16.
__device__ __forceinline__ float fast_tanh(float x) {
    float t = __expf(-2.0f * fabsf(x));
    float r = __fdividef(1.0f - t, 1.0f + t);
    return copysignf(r, x);
}

__global__ void __launch_bounds__(256, 2)
energy_mma(const float* __restrict__ enc, const float* __restrict__ v) {
    extern __shared__ __align__(1024) char smem[];
    const uint32_t sb  = smem_u32(smem);
    const int tid  = threadIdx.x;
    const int wid  = tid >> 5;
    const int lane = tid & 31;
    const int oBase   = blockIdx.x * 128;
    const int rowBase = blockIdx.y * 128;
    const int b       = rowBase >> 11;

    const int warpM = (wid & 3) * 32;    // 0,32,64,96
    const int warpN = (wid >> 2) * 64;   // 0 or 64

    if (tid < 128) {
        ((float*)(smem + SM_BIAS))[tid] = g_bias2[b * H_ + oBase + tid];
        ((float*)(smem + SM_V))[tid]    = v[oBase + tid];
    }

    // ---- A loader mapping: 8 threads/row, 32 rows/pass, 4 passes
    const int crow = tid >> 3;           // 0..31
    const int cf   = tid & 7;            // float4 index within 32-float chunk
    const float* aSrc = enc + (size_t)(rowBase + crow) * H_ + cf * 4;
    uint32_t dOff[4];
#pragma unroll
    for (int p = 0; p < 4; ++p) {
        const int row = p * 32 + crow;
        dOff[p] = row * 64 + (((cf >> 1) ^ ((row >> 1) & 3)) << 4) + (cf & 1) * 8;
    }

    // ---- B loader mapping: 2 threads/row, two 16B chunks each
    const int brow = tid >> 1;           // 0..127
    const int bcc  = (tid & 1) * 2;      // chunk pair {bcc, bcc+1}
    const __half* bSrc = g_W16 + (size_t)(oBase + brow) * H_;
    const uint32_t bDst0 = (uint32_t)(BF_BH + brow * 64 +
                           (((bcc + 0) ^ ((brow >> 1) & 3)) << 4));
    const uint32_t bDst1 = (uint32_t)(BF_BH + brow * 64 +
                           (((bcc + 1) ^ ((brow >> 1) & 3)) << 4));

    float4 areg[4];                      // A prefetch (live across one MMA)

#define LDG_A(c)                                                               \
    do {                                                                       \
        _Pragma("unroll")                                                      \
        for (int p = 0; p < 4; ++p)                                            \
            areg[p] = *(const float4*)(aSrc + (size_t)p * 32 * H_ + (c) * 32); \
    } while (0)

#define CP_B16(c, bufsel)                                                      \
    do {                                                                       \
        const uint32_t _bb = sb + SM_BF + (bufsel) * BF_BUF;                   \
        cp_async16(_bb + bDst0, bSrc + (c) * 32 + (bcc + 0) * 8);              \
        cp_async16(_bb + bDst1, bSrc + (c) * 32 + (bcc + 1) * 8);              \
        cp_commit();                                                           \
    } while (0)

#define CONVERT_A(bufsel)                                                      \
    do {                                                                       \
        char* _buf = (char*)smem + SM_BF + (bufsel) * BF_BUF;                  \
        _Pragma("unroll")                                                      \
        for (int p = 0; p < 4; ++p) split_store_f16(areg[p], _buf + dOff[p]);  \
    } while (0)

    // ---- mma fragment mapping (lane math validated R6-R12)
    const int rA = (lane & 7) + (((lane >> 3) & 1) << 3);
    const int gA = (lane >> 4) & 1;
    const int rB = (lane & 7) + (((lane >> 4) & 1) << 3);
    const int gB = (lane >> 3) & 1;
    const int xA2 = (rA >> 1) & 3;
    const int xB2 = (rB >> 1) & 3;

    float acc[2][8][4];
#pragma unroll
    for (int i = 0; i < 2; ++i)
#pragma unroll
        for (int j = 0; j < 8; ++j)
#pragma unroll
            for (int k = 0; k < 4; ++k) acc[i][j][k] = 0.0f;

    // ---- prologue: chunk 0 into buf 0; areg <- chunk 1
    CP_B16(0, 0);
    LDG_A(0);
    CONVERT_A(0);
    LDG_A(1);
    cp_wait0();
    __syncthreads();

#pragma unroll 1
    for (int kt = 0; kt < 32; ++kt) {
        // producer work FIRST (targets the other buffer; hides under MMA):
        // B(kt+1) cp.async, A(kt+1) convert from areg, then areg <- A(kt+2)
        if (kt + 1 < 32) {
            CP_B16(kt + 1, (kt + 1) & 1);
            CONVERT_A((kt + 1) & 1);
        }
        if (kt + 2 < 32) LDG_A(kt + 2);

        // mma on buf kt&1 (ready; synced)
        {
            const uint32_t bufb = sb + SM_BF + (kt & 1) * BF_BUF;
            const uint32_t AH = bufb;
            const uint32_t AL = bufb + 8192;
            const uint32_t BH = bufb + BF_BH;
#pragma unroll
            for (int k16 = 0; k16 < 2; ++k16) {
                const int cA = ((2 * k16 + gA) ^ xA2) << 4;
                const int cB = ((2 * k16 + gB) ^ xB2) << 4;
                uint32_t ah[2][4], bh[4][4];
#pragma unroll
                for (int mi = 0; mi < 2; ++mi)
                    ldsm4(ah[mi], AH + (warpM + mi * 16 + rA) * 64 + cA);
#pragma unroll
                for (int np = 0; np < 4; ++np)
                    ldsm4(bh[np], BH + (warpN + np * 16 + rB) * 64 + cB);
                // product 1: xh * wh
#pragma unroll
                for (int mi = 0; mi < 2; ++mi)
#pragma unroll
                    for (int ni = 0; ni < 8; ++ni)
                        mma16816(acc[mi][ni], ah[mi],
                                 bh[ni >> 1][(ni & 1) * 2], bh[ni >> 1][(ni & 1) * 2 + 1]);
                // product 2: xl * wh
                uint32_t al[2][4];
#pragma unroll
                for (int mi = 0; mi < 2; ++mi)
                    ldsm4(al[mi], AL + (warpM + mi * 16 + rA) * 64 + cA);
#pragma unroll
                for (int mi = 0; mi < 2; ++mi)
#pragma unroll
                    for (int ni = 0; ni < 8; ++ni)
                        mma16816(acc[mi][ni], al[mi],
                                 bh[ni >> 1][(ni & 1) * 2], bh[ni >> 1][(ni & 1) * 2 + 1]);
            }
        }

        cp_wait0();
        __syncthreads();
    }

    // ---- epilogue: tanh(acc + bias2)*v, reduce over n, atomicAdd scores ----
    const float* sbias = (const float*)(smem + SM_BIAS);
    const float* sv    = (const float*)(smem + SM_V);
    const int q = lane & 3;
    const int r = lane >> 2;

#pragma unroll
    for (int mi = 0; mi < 2; ++mi) {
        float pa = 0.0f, pb = 0.0f;
#pragma unroll
        for (int ni = 0; ni < 8; ++ni) {
            const int n0 = warpN + ni * 8 + 2 * q;
            const float b0 = sbias[n0], b1 = sbias[n0 + 1];
            const float v0 = sv[n0],    v1 = sv[n0 + 1];
            pa += fast_tanh(acc[mi][ni][0] + b0) * v0 +
                  fast_tanh(acc[mi][ni][1] + b1) * v1;
            pb += fast_tanh(acc[mi][ni][2] + b0) * v0 +
                  fast_tanh(acc[mi][ni][3] + b1) * v1;
        }
        pa += __shfl_xor_sync(0xffffffffu, pa, 1);
        pa += __shfl_xor_sync(0xffffffffu, pa, 2);
        pb += __shfl_xor_sync(0xffffffffu, pb, 1);
        pb += __shfl_xor_sync(0xffffffffu, pb, 2);
        if (q == 0) {
            const int m = rowBase + warpM + mi * 16 + r;
            atomicAdd(&g_scores[m], pa);
            atomicAdd(&g_scores[m + 8], pb);
        }
    }
}

// ---------------- kernel 3: softmax over S per batch ------------------------
__global__ void softmax_kernel(float* __restrict__ attn) {
    __shared__ float red[8];
    const int b = blockIdx.x, t = threadIdx.x;
    const float* s = g_scores + b * S_;

    float loc[8];
    float mx = -1e30f;
#pragma unroll
    for (int i = 0; i < 8; ++i) {
        loc[i] = s[t + i * 256];
        mx = fmaxf(mx, loc[i]);
    }
#pragma unroll
    for (int off = 16; off; off >>= 1)
        mx = fmaxf(mx, __shfl_xor_sync(0xffffffffu, mx, off));
    if ((t & 31) == 0) red[t >> 5] = mx;
    __syncthreads();
    float bm = red[0];
#pragma unroll
    for (int w = 1; w < 8; ++w) bm = fmaxf(bm, red[w]);
    __syncthreads();

    float sum = 0.0f;
#pragma unroll
    for (int i = 0; i < 8; ++i) {
        loc[i] = expf(loc[i] - bm);
        sum += loc[i];
    }
#pragma unroll
    for (int off = 16; off; off >>= 1)
        sum += __shfl_xor_sync(0xffffffffu, sum, off);
    if ((t & 31) == 0) red[t >> 5] = sum;
    __syncthreads();
    float bs = 0.0f;
#pragma unroll
    for (int w = 0; w < 8; ++w) bs += red[w];

    const float inv = 1.0f / bs;
#pragma unroll
    for (int i = 0; i < 8; ++i)
        attn[b * S_ + t + i * 256] = loc[i] * inv;
}

// ---------------- kernel 4: context = attn @ enc ----------------------------
__global__ void context_kernel(const float* __restrict__ enc,
                               const float* __restrict__ attn,
                               float* __restrict__ ctx) {
    __shared__ float ws[128];
    const int b  = blockIdx.x;
    const int s0 = blockIdx.y * 128;
    if (threadIdx.x < 128) ws[threadIdx.x] = attn[b * S_ + s0 + threadIdx.x];
    __syncthreads();

    const int h = threadIdx.x * 4;
    float4 acc = make_float4(0.f, 0.f, 0.f, 0.f);
    const float* base = enc + ((size_t)b * S_ + s0) * H_ + h;
#pragma unroll 4
    for (int s = 0; s < 128; ++s) {
        const float w = ws[s];
        float4 e = *(const float4*)(base + (size_t)s * H_);
        acc.x += w * e.x;  acc.y += w * e.y;
        acc.z += w * e.z;  acc.w += w * e.w;
    }
    atomicAdd(&ctx[b * H_ + h + 0], acc.x);
    atomicAdd(&ctx[b * H_ + h + 1], acc.y);
    atomicAdd(&ctx[b * H_ + h + 2], acc.z);
    atomicAdd(&ctx[b * H_ + h + 3], acc.w);
}

// ---------------- launch ----------------------------------------------------
extern "C" void kernel_launch(void* const* d_in, const int* in_sizes, int n_in,
                              void* d_out, int out_size) {
    const float* hidden = (const float*)d_in[0];   // [B,H]
    const float* enc    = (const float*)d_in[1];   // [B,S,H]
    const float* W      = (const float*)d_in[2];   // [H,H]
    const float* b_attn = (const float*)d_in[3];   // [H]
    const float* v      = (const float*)d_in[4];   // [H]

    float* out  = (float*)d_out;
    float* ctx  = out;             // [B,H]
    float* attn = out + B_ * H_;   // [B,S]

    // idempotent, executed every call (no static guards)
    cudaFuncSetAttribute((const void*)energy_mma,
                         cudaFuncAttributeMaxDynamicSharedMemorySize, SM_TOTAL);

    zero_kernel<<<256, 256>>>(ctx);
    w16_kernel<<<(H_ * H_ / 4) / 256, 256>>>(W);
    bias2_kernel<<<H_ / 8, 256>>>(hidden, W, b_attn);
    energy_mma<<<dim3(H_ / 128, BS_ / 128), 256, SM_TOTAL>>>(enc, v);
    softmax_kernel<<<B_, 256>>>(attn);
    context_kernel<<<dim3(B_, 16), 256>>>(enc, attn, ctx);
}

// round 14
// speedup vs baseline: 1.0398x; 1.0398x over previous
#include <cuda_runtime.h>
#include <cuda_fp16.h>
#include <math.h>
#include <stdint.h>

#define B_  32
#define S_  2048
#define H_  1024
#define BS_ (B_ * S_)

// ---------------- scratch (small device globals only) -----------------------
__device__ __align__(1024) float g_scores[BS_];     // [B,S] logits
__device__ __align__(1024) float g_bias2[B_ * H_];  // [B,H]

// =================== PTX helpers ============================================
__device__ __forceinline__ uint32_t smem_u32(const void* p) {
    uint32_t a;
    asm("{ .reg .u64 t; cvta.to.shared.u64 t, %1; cvt.u32.u64 %0, t; }"
        : "=r"(a) : "l"(p));
    return a;
}
__device__ __forceinline__ void ldsm4(uint32_t r[4], uint32_t addr) {
    asm volatile("ldmatrix.sync.aligned.m8n8.x4.shared.b16 {%0,%1,%2,%3}, [%4];"
                 : "=r"(r[0]), "=r"(r[1]), "=r"(r[2]), "=r"(r[3]) : "r"(addr));
}
__device__ __forceinline__ void mma16816(float c[4], const uint32_t a[4],
                                         uint32_t b0, uint32_t b1) {
    asm volatile(
        "mma.sync.aligned.m16n8k16.row.col.f32.f16.f16.f32 "
        "{%0,%1,%2,%3}, {%4,%5,%6,%7}, {%8,%9}, {%0,%1,%2,%3};"
        : "+f"(c[0]), "+f"(c[1]), "+f"(c[2]), "+f"(c[3])
        : "r"(a[0]), "r"(a[1]), "r"(a[2]), "r"(a[3]), "r"(b0), "r"(b1));
}
__device__ __forceinline__ void cp_async16(uint32_t dst, const void* src) {
    asm volatile("cp.async.cg.shared.global [%0], [%1], 16;"
                 :: "r"(dst), "l"(src) : "memory");
}
__device__ __forceinline__ void cp_commit() {
    asm volatile("cp.async.commit_group;" ::: "memory");
}
__device__ __forceinline__ void cp_wait0() {
    asm volatile("cp.async.wait_group 0;" ::: "memory");
}

// fp16 rn split of one float4: xh = rn_f16(x), xl = rn_f16(x - xh).
// dst_hi = hi-plane location; lo plane is +8192 bytes.
__device__ __forceinline__ void split_store_f16(const float4 val, char* dst_hi) {
    const __half h0 = __float2half_rn(val.x);
    const __half h1 = __float2half_rn(val.y);
    const __half h2 = __float2half_rn(val.z);
    const __half h3 = __float2half_rn(val.w);
    __half2 hw0 = __halves2half2(h0, h1);
    __half2 hw1 = __halves2half2(h2, h3);
    const __half l0 = __float2half_rn(val.x - __half2float(h0));
    const __half l1 = __float2half_rn(val.y - __half2float(h1));
    const __half l2 = __float2half_rn(val.z - __half2float(h2));
    const __half l3 = __float2half_rn(val.w - __half2float(h3));
    __half2 lw0 = __halves2half2(l0, l1);
    __half2 lw1 = __halves2half2(l2, l3);
    ((__half2*)dst_hi)[0] = hw0;
    ((__half2*)dst_hi)[1] = hw1;
    ((__half2*)(dst_hi + 8192))[0] = lw0;
    ((__half2*)(dst_hi + 8192))[1] = lw1;
}

// single-plane fp16 rn convert of one float4
__device__ __forceinline__ void cvt_store_f16(const float4 val, char* dst) {
    __half2 w0 = __halves2half2(__float2half_rn(val.x), __float2half_rn(val.y));
    __half2 w1 = __halves2half2(__float2half_rn(val.z), __float2half_rn(val.w));
    ((__half2*)dst)[0] = w0;
    ((__half2*)dst)[1] = w1;
}

// ---------------- SMEM layout for energy_mma --------------------------------
// bias 0..512 | v 512..1024 | B fp32 slots 1024..17408 |
// fp16 double buffer @17408: 2 x 24KB (AH 0 | AL 8K | BH 16K)
#define SM_BIAS   0
#define SM_V      512
#define SM_F32    1024
#define SM_BF     17408
#define BF_BUF    24576
#define BF_BH     16384
#define SM_TOTAL  (SM_BF + 2 * BF_BUF)    // 66560 -> 2 CTAs/SM

// ---------------- kernel 0: zero scores + context region --------------------
__global__ void zero_kernel(float* __restrict__ ctx) {
    int i = blockIdx.x * blockDim.x + threadIdx.x;
    if (i < BS_)      g_scores[i] = 0.0f;
    if (i < B_ * H_)  ctx[i]      = 0.0f;
}

// ---------------- kernel 1: bias2 = hidden @ W^T + b_attn (R12 version) -----
// grid H/8 blocks; warp w owns output o; W row read ONCE into registers,
// hidden[b] staged in smem per b. L2 traffic 128MB -> ~20MB.
__global__ void bias2_kernel(const float* __restrict__ hidden,
                             const float* __restrict__ W,
                             const float* __restrict__ b_attn) {
    __shared__ float sh[H_];
    const int w    = threadIdx.x >> 5;
    const int lane = threadIdx.x & 31;
    const int o    = blockIdx.x * 8 + w;

    float4 wr[8];
    const float4* wrow = (const float4*)(W + (size_t)o * H_);
#pragma unroll
    for (int i = 0; i < 8; ++i) wr[i] = wrow[lane + i * 32];
    const float ba = b_attn[o];

    for (int b = 0; b < B_; ++b) {
        __syncthreads();
#pragma unroll
        for (int i = threadIdx.x; i < H_; i += 256) sh[i] = hidden[b * H_ + i];
        __syncthreads();

        float sum = 0.0f;
#pragma unroll
        for (int i = 0; i < 8; ++i) {
            float4 h = *(const float4*)(sh + (lane + i * 32) * 4);
            sum += wr[i].x * h.x + wr[i].y * h.y + wr[i].z * h.z + wr[i].w * h.w;
        }
#pragma unroll
        for (int off = 16; off; off >>= 1)
            sum += __shfl_xor_sync(0xffffffffu, sum, off);
        if (lane == 0) g_bias2[b * H_ + o] = sum + ba;
    }
}

// ---------------- kernel 2: fp16 2-product split GEMM (R11 version) ---------
// scores[b,s] += sum_o v[o]*tanh(enc[s]·W[o] + bias2[b,o])
// x*w ~ xh*wh + xl*wh (= x*wh exactly); dropped term x*wl ~ 2^-12.
__device__ __forceinline__ float fast_tanh(float x) {
    float t = __expf(-2.0f * fabsf(x));
    float r = __fdividef(1.0f - t, 1.0f + t);
    return copysignf(r, x);
}

__global__ void __launch_bounds__(256, 2)
energy_mma(const float* __restrict__ enc, const float* __restrict__ W,
           const float* __restrict__ v) {
    extern __shared__ __align__(1024) char smem[];
    const uint32_t sb  = smem_u32(smem);
    const int tid  = threadIdx.x;
    const int wid  = tid >> 5;
    const int lane = tid & 31;
    const int oBase   = blockIdx.x * 128;
    const int rowBase = blockIdx.y * 128;
    const int b       = rowBase >> 11;

    const int warpM = (wid >> 2) * 64;
    const int warpN = (wid & 3) * 32;

    if (tid < 128) {
        ((float*)(smem + SM_BIAS))[tid] = g_bias2[b * H_ + oBase + tid];
        ((float*)(smem + SM_V))[tid]    = v[oBase + tid];
    }

    // ---- loader mapping: 8 threads/row, 32 rows/pass, 4 passes
    const int crow = tid >> 3;           // 0..31
    const int cf   = tid & 7;            // float4 index within 32-float chunk
    const float* aSrc = enc + (size_t)(rowBase + crow) * H_ + cf * 4;
    const float* bSrc = W   + (size_t)(oBase  + crow) * H_ + cf * 4;
#define SLOT(j) (sb + SM_F32 + ((((j) << 8) + tid) << 4))
    uint32_t dOff[4];
#pragma unroll
    for (int p = 0; p < 4; ++p) {
        const int row = p * 32 + crow;
        dOff[p] = row * 64 + (((cf >> 1) ^ ((row >> 1) & 3)) << 4) + (cf & 1) * 8;
    }

    // A chunk prefetch registers (live across one MMA block)
    float4 areg[4];

#define LDG_A(c)                                                               \
    do {                                                                       \
        _Pragma("unroll")                                                      \
        for (int p = 0; p < 4; ++p)                                            \
            areg[p] = *(const float4*)(aSrc + (size_t)p * 32 * H_ + (c) * 32); \
    } while (0)

#define CP_B(c)                                                                \
    do {                                                                       \
        _Pragma("unroll")                                                      \
        for (int p = 0; p < 4; ++p)                                            \
            cp_async16(SLOT(p), bSrc + (size_t)p * 32 * H_ + (c) * 32);        \
        cp_commit();                                                           \
    } while (0)

    // convert A (from regs, 2 planes) + B (from slots, 1 plane) into buffer
#define CONVERT(bufsel)                                                        \
    do {                                                                       \
        char* _buf = (char*)smem + SM_BF + (bufsel) * BF_BUF;                  \
        cp_wait0();                                                            \
        _Pragma("unroll")                                                      \
        for (int p = 0; p < 4; ++p) split_store_f16(areg[p], _buf + dOff[p]);  \
        _Pragma("unroll")                                                      \
        for (int j = 0; j < 4; ++j) {                                          \
            float4 bx;                                                         \
            asm volatile("ld.shared.v4.b32 {%0,%1,%2,%3}, [%4];"               \
                : "=f"(bx.x), "=f"(bx.y), "=f"(bx.z), "=f"(bx.w)               \
                : "r"(SLOT(j)));                                               \
            cvt_store_f16(bx, _buf + BF_BH + dOff[j]);                         \
        }                                                                      \
    } while (0)

    // ---- mma fragment mapping (validated R6-R13)
    const int rA = (lane & 7) + (((lane >> 3) & 1) << 3);
    const int gA = (lane >> 4) & 1;
    const int rB = (lane & 7) + (((lane >> 4) & 1) << 3);
    const int gB = (lane >> 3) & 1;
    const int xA2 = (rA >> 1) & 3;
    const int xB2 = (rB >> 1) & 3;

    float acc[4][4][4];
#pragma unroll
    for (int i = 0; i < 4; ++i)
#pragma unroll
        for (int j = 0; j < 4; ++j)
#pragma unroll
            for (int k = 0; k < 4; ++k) acc[i][j][k] = 0.0f;

    // ---- prologue: chunk 0 converted into buf 0; chunk 1 in flight
    CP_B(0);
    LDG_A(0);
    CONVERT(0);
    CP_B(1);
    LDG_A(1);
    __syncthreads();

#pragma unroll 1
    for (int kt = 0; kt < 32; ++kt) {
        // mma on fp16 buf kt&1 (ready; synced). areg holds chunk kt+1.
        {
            const uint32_t bufb = sb + SM_BF + (kt & 1) * BF_BUF;
            const uint32_t AH = bufb;
            const uint32_t AL = bufb + 8192;
            const uint32_t BH = bufb + BF_BH;
#pragma unroll
            for (int k16 = 0; k16 < 2; ++k16) {
                const int cA = ((2 * k16 + gA) ^ xA2) << 4;
                const int cB = ((2 * k16 + gB) ^ xB2) << 4;
                uint32_t ah[4][4], bh[2][4];
#pragma unroll
                for (int mi = 0; mi < 4; ++mi)
                    ldsm4(ah[mi], AH + (warpM + mi * 16 + rA) * 64 + cA);
#pragma unroll
                for (int np = 0; np < 2; ++np)
                    ldsm4(bh[np], BH + (warpN + np * 16 + rB) * 64 + cB);
                // product 1: xh * wh
#pragma unroll
                for (int mi = 0; mi < 4; ++mi)
#pragma unroll
                    for (int ni = 0; ni < 4; ++ni)
                        mma16816(acc[mi][ni], ah[mi],
                                 bh[ni >> 1][(ni & 1) * 2], bh[ni >> 1][(ni & 1) * 2 + 1]);
                // product 2: xl * wh (al reuses ah's registers)
                uint32_t al[4][4];
#pragma unroll
                for (int mi = 0; mi < 4; ++mi)
                    ldsm4(al[mi], AL + (warpM + mi * 16 + rA) * 64 + cA);
#pragma unroll
                for (int mi = 0; mi < 4; ++mi)
#pragma unroll
                    for (int ni = 0; ni < 4; ++ni)
                        mma16816(acc[mi][ni], al[mi],
                                 bh[ni >> 1][(ni & 1) * 2], bh[ni >> 1][(ni & 1) * 2 + 1]);
            }
        }

        // convert chunk kt+1 into buf (kt+1)&1, then start chunk kt+2 loads
        if (kt + 1 < 32) CONVERT((kt + 1) & 1);
        if (kt + 2 < 32) {
            CP_B(kt + 2);
            LDG_A(kt + 2);
        }
        __syncthreads();
    }

    // ---- epilogue: tanh(acc + bias2)*v, reduce over n, atomicAdd scores ----
    const float* sbias = (const float*)(smem + SM_BIAS);
    const float* sv    = (const float*)(smem + SM_V);
    const int q = lane & 3;
    const int r = lane >> 2;

#pragma unroll
    for (int mi = 0; mi < 4; ++mi) {
        float pa = 0.0f, pb = 0.0f;
#pragma unroll
        for (int ni = 0; ni < 4; ++ni) {
            const int n0 = warpN + ni * 8 + 2 * q;
            const float b0 = sbias[n0], b1 = sbias[n0 + 1];
            const float v0 = sv[n0],    v1 = sv[n0 + 1];
            pa += fast_tanh(acc[mi][ni][0] + b0) * v0 +
                  fast_tanh(acc[mi][ni][1] + b1) * v1;
            pb += fast_tanh(acc[mi][ni][2] + b0) * v0 +
                  fast_tanh(acc[mi][ni][3] + b1) * v1;
        }
        pa += __shfl_xor_sync(0xffffffffu, pa, 1);
        pa += __shfl_xor_sync(0xffffffffu, pa, 2);
        pb += __shfl_xor_sync(0xffffffffu, pb, 1);
        pb += __shfl_xor_sync(0xffffffffu, pb, 2);
        if (q == 0) {
            const int m = rowBase + warpM + mi * 16 + r;
            atomicAdd(&g_scores[m], pa);
            atomicAdd(&g_scores[m + 8], pb);
        }
    }
}

// ---------------- kernel 3: softmax over S per batch ------------------------
__global__ void softmax_kernel(float* __restrict__ attn) {
    __shared__ float red[8];
    const int b = blockIdx.x, t = threadIdx.x;
    const float* s = g_scores + b * S_;

    float loc[8];
    float mx = -1e30f;
#pragma unroll
    for (int i = 0; i < 8; ++i) {
        loc[i] = s[t + i * 256];
        mx = fmaxf(mx, loc[i]);
    }
#pragma unroll
    for (int off = 16; off; off >>= 1)
        mx = fmaxf(mx, __shfl_xor_sync(0xffffffffu, mx, off));
    if ((t & 31) == 0) red[t >> 5] = mx;
    __syncthreads();
    float bm = red[0];
#pragma unroll
    for (int w = 1; w < 8; ++w) bm = fmaxf(bm, red[w]);
    __syncthreads();

    float sum = 0.0f;
#pragma unroll
    for (int i = 0; i < 8; ++i) {
        loc[i] = expf(loc[i] - bm);
        sum += loc[i];
    }
#pragma unroll
    for (int off = 16; off; off >>= 1)
        sum += __shfl_xor_sync(0xffffffffu, sum, off);
    if ((t & 31) == 0) red[t >> 5] = sum;
    __syncthreads();
    float bs = 0.0f;
#pragma unroll
    for (int w = 0; w < 8; ++w) bs += red[w];

    const float inv = 1.0f / bs;
#pragma unroll
    for (int i = 0; i < 8; ++i)
        attn[b * S_ + t + i * 256] = loc[i] * inv;
}

// ---------------- kernel 4: context = attn @ enc ----------------------------
__global__ void context_kernel(const float* __restrict__ enc,
                               const float* __restrict__ attn,
                               float* __restrict__ ctx) {
    __shared__ float ws[128];
    const int b  = blockIdx.x;
    const int s0 = blockIdx.y * 128;
    if (threadIdx.x < 128) ws[threadIdx.x] = attn[b * S_ + s0 + threadIdx.x];
    __syncthreads();

    const int h = threadIdx.x * 4;
    float4 acc = make_float4(0.f, 0.f, 0.f, 0.f);
    const float* base = enc + ((size_t)b * S_ + s0) * H_ + h;
#pragma unroll 4
    for (int s = 0; s < 128; ++s) {
        const float w = ws[s];
        float4 e = *(const float4*)(base + (size_t)s * H_);
        acc.x += w * e.x;  acc.y += w * e.y;
        acc.z += w * e.z;  acc.w += w * e.w;
    }
    atomicAdd(&ctx[b * H_ + h + 0], acc.x);
    atomicAdd(&ctx[b * H_ + h + 1], acc.y);
    atomicAdd(&ctx[b * H_ + h + 2], acc.z);
    atomicAdd(&ctx[b * H_ + h + 3], acc.w);
}

// ---------------- launch ----------------------------------------------------
extern "C" void kernel_launch(void* const* d_in, const int* in_sizes, int n_in,
                              void* d_out, int out_size) {
    const float* hidden = (const float*)d_in[0];   // [B,H]
    const float* enc    = (const float*)d_in[1];   // [B,S,H]
    const float* W      = (const float*)d_in[2];   // [H,H]
    const float* b_attn = (const float*)d_in[3];   // [H]
    const float* v      = (const float*)d_in[4];   // [H]

    float* out  = (float*)d_out;
    float* ctx  = out;             // [B,H]
    float* attn = out + B_ * H_;   // [B,S]

    // idempotent, executed every call (no static guards)
    cudaFuncSetAttribute((const void*)energy_mma,
                         cudaFuncAttributeMaxDynamicSharedMemorySize, SM_TOTAL);

    zero_kernel<<<256, 256>>>(ctx);
    bias2_kernel<<<H_ / 8, 256>>>(hidden, W, b_attn);
    energy_mma<<<dim3(H_ / 128, BS_ / 128), 256, SM_TOTAL>>>(enc, W, v);
    softmax_kernel<<<B_, 256>>>(attn);
    context_kernel<<<dim3(B_, 16), 256>>>(enc, attn, ctx);
}

// round 15
// speedup vs baseline: 1.0888x; 1.0472x over previous
#include <cuda_runtime.h>
#include <cuda_fp16.h>
#include <math.h>
#include <stdint.h>

#define B_  32
#define S_  2048
#define H_  1024
#define BS_ (B_ * S_)

// ---------------- scratch (small device globals only) -----------------------
__device__ __align__(1024) float g_scores[BS_];     // [B,S] logits
__device__ __align__(1024) float g_bias2[B_ * H_];  // [B,H]

// =================== PTX helpers ============================================
__device__ __forceinline__ uint32_t smem_u32(const void* p) {
    uint32_t a;
    asm("{ .reg .u64 t; cvta.to.shared.u64 t, %1; cvt.u32.u64 %0, t; }"
        : "=r"(a) : "l"(p));
    return a;
}
__device__ __forceinline__ void ldsm4(uint32_t r[4], uint32_t addr) {
    asm volatile("ldmatrix.sync.aligned.m8n8.x4.shared.b16 {%0,%1,%2,%3}, [%4];"
                 : "=r"(r[0]), "=r"(r[1]), "=r"(r[2]), "=r"(r[3]) : "r"(addr));
}
__device__ __forceinline__ void mma16816(float c[4], const uint32_t a[4],
                                         uint32_t b0, uint32_t b1) {
    asm volatile(
        "mma.sync.aligned.m16n8k16.row.col.f32.f16.f16.f32 "
        "{%0,%1,%2,%3}, {%4,%5,%6,%7}, {%8,%9}, {%0,%1,%2,%3};"
        : "+f"(c[0]), "+f"(c[1]), "+f"(c[2]), "+f"(c[3])
        : "r"(a[0]), "r"(a[1]), "r"(a[2]), "r"(a[3]), "r"(b0), "r"(b1));
}
__device__ __forceinline__ void cp_async16(uint32_t dst, const void* src) {
    asm volatile("cp.async.cg.shared.global [%0], [%1], 16;"
                 :: "r"(dst), "l"(src) : "memory");
}
__device__ __forceinline__ void cp_commit() {
    asm volatile("cp.async.commit_group;" ::: "memory");
}
__device__ __forceinline__ void cp_wait0() {
    asm volatile("cp.async.wait_group 0;" ::: "memory");
}

// fp16 rn split of one float4: xh = rn_f16(x), xl = rn_f16(x - xh).
// dst_hi = hi-plane location; lo plane is +8192 bytes.
__device__ __forceinline__ void split_store_f16(const float4 val, char* dst_hi) {
    const __half h0 = __float2half_rn(val.x);
    const __half h1 = __float2half_rn(val.y);
    const __half h2 = __float2half_rn(val.z);
    const __half h3 = __float2half_rn(val.w);
    __half2 hw0 = __halves2half2(h0, h1);
    __half2 hw1 = __halves2half2(h2, h3);
    const __half l0 = __float2half_rn(val.x - __half2float(h0));
    const __half l1 = __float2half_rn(val.y - __half2float(h1));
    const __half l2 = __float2half_rn(val.z - __half2float(h2));
    const __half l3 = __float2half_rn(val.w - __half2float(h3));
    __half2 lw0 = __halves2half2(l0, l1);
    __half2 lw1 = __halves2half2(l2, l3);
    ((__half2*)dst_hi)[0] = hw0;
    ((__half2*)dst_hi)[1] = hw1;
    ((__half2*)(dst_hi + 8192))[0] = lw0;
    ((__half2*)(dst_hi + 8192))[1] = lw1;
}

// single-plane fp16 rn convert of one float4
__device__ __forceinline__ void cvt_store_f16(const float4 val, char* dst) {
    __half2 w0 = __halves2half2(__float2half_rn(val.x), __float2half_rn(val.y));
    __half2 w1 = __halves2half2(__float2half_rn(val.z), __float2half_rn(val.w));
    ((__half2*)dst)[0] = w0;
    ((__half2*)dst)[1] = w1;
}

// ---------------- SMEM layout for energy_mma --------------------------------
// bias 0..512 | v 512..1024 | B fp32 slots 1024..17408 |
// fp16 double buffer @17408: 2 x 24KB (AH 0 | AL 8K | BH 16K)
#define SM_BIAS   0
#define SM_V      512
#define SM_F32    1024
#define SM_BF     17408
#define BF_BUF    24576
#define BF_BH     16384
#define SM_TOTAL  (SM_BF + 2 * BF_BUF)    // 66560 -> 2 CTAs/SM

// ---------------- kernel 0: zero scores + context region --------------------
__global__ void zero_kernel(float* __restrict__ ctx) {
    int i = blockIdx.x * blockDim.x + threadIdx.x;
    if (i < BS_)      g_scores[i] = 0.0f;
    if (i < B_ * H_)  ctx[i]      = 0.0f;
}

// ---------------- kernel 1: bias2 = hidden @ W^T + b_attn (R11 version) -----
__global__ void bias2_kernel(const float* __restrict__ hidden,
                             const float* __restrict__ W,
                             const float* __restrict__ b_attn) {
    __shared__ float sh[H_];
    const int b = blockIdx.x;
    for (int i = threadIdx.x; i < H_; i += blockDim.x) sh[i] = hidden[b * H_ + i];
    __syncthreads();

    const int w    = threadIdx.x >> 5;
    const int lane = threadIdx.x & 31;
    const int o    = blockIdx.y * 8 + w;
    const float* wr = W + (size_t)o * H_;

    float sum = 0.0f;
#pragma unroll
    for (int h = lane * 4; h < H_; h += 128) {
        float4 wv = *(const float4*)(wr + h);
        float4 xv = *(const float4*)(sh + h);
        sum += wv.x * xv.x + wv.y * xv.y + wv.z * xv.z + wv.w * xv.w;
    }
#pragma unroll
    for (int off = 16; off; off >>= 1)
        sum += __shfl_xor_sync(0xffffffffu, sum, off);
    if (lane == 0) g_bias2[b * H_ + o] = sum + b_attn[o];
}

// ---------------- kernel 2: fp16 2-product split GEMM + tanh + dot(v) -------
// scores[b,s] += sum_o v[o]*tanh(enc[s]·W[o] + bias2[b,o])
// x*w ~ xh*wh + xl*wh (= x*wh exactly); dropped term x*wl ~ 2^-12.
__device__ __forceinline__ float fast_tanh(float x) {
    float t = __expf(-2.0f * fabsf(x));
    float r = __fdividef(1.0f - t, 1.0f + t);
    return copysignf(r, x);
}

__global__ void __launch_bounds__(256, 2)
energy_mma(const float* __restrict__ enc, const float* __restrict__ W,
           const float* __restrict__ v) {
    extern __shared__ __align__(1024) char smem[];
    const uint32_t sb  = smem_u32(smem);
    const int tid  = threadIdx.x;
    const int wid  = tid >> 5;
    const int lane = tid & 31;
    const int oBase   = blockIdx.x * 128;
    const int rowBase = blockIdx.y * 128;
    const int b       = rowBase >> 11;

    const int warpM = (wid >> 2) * 64;
    const int warpN = (wid & 3) * 32;

    if (tid < 128) {
        ((float*)(smem + SM_BIAS))[tid] = g_bias2[b * H_ + oBase + tid];
        ((float*)(smem + SM_V))[tid]    = v[oBase + tid];
    }

    // ---- loader mapping: 8 threads/row, 32 rows/pass, 4 passes
    const int crow = tid >> 3;           // 0..31
    const int cf   = tid & 7;            // float4 index within 32-float chunk
    const float* aSrc = enc + (size_t)(rowBase + crow) * H_ + cf * 4;
    const float* bSrc = W   + (size_t)(oBase  + crow) * H_ + cf * 4;
#define SLOT(j) (sb + SM_F32 + ((((j) << 8) + tid) << 4))
    uint32_t dOff[4];
#pragma unroll
    for (int p = 0; p < 4; ++p) {
        const int row = p * 32 + crow;
        dOff[p] = row * 64 + (((cf >> 1) ^ ((row >> 1) & 3)) << 4) + (cf & 1) * 8;
    }

    // A chunk prefetch registers (live across one MMA block)
    float4 areg[4];

#define LDG_A(c)                                                               \
    do {                                                                       \
        _Pragma("unroll")                                                      \
        for (int p = 0; p < 4; ++p)                                            \
            areg[p] = *(const float4*)(aSrc + (size_t)p * 32 * H_ + (c) * 32); \
    } while (0)

#define CP_B(c)                                                                \
    do {                                                                       \
        _Pragma("unroll")                                                      \
        for (int p = 0; p < 4; ++p)                                            \
            cp_async16(SLOT(p), bSrc + (size_t)p * 32 * H_ + (c) * 32);        \
        cp_commit();                                                           \
    } while (0)

    // convert A (from regs, 2 planes) + B (from slots, 1 plane) into buffer
#define CONVERT(bufsel)                                                        \
    do {                                                                       \
        char* _buf = (char*)smem + SM_BF + (bufsel) * BF_BUF;                  \
        cp_wait0();                                                            \
        _Pragma("unroll")                                                      \
        for (int p = 0; p < 4; ++p) split_store_f16(areg[p], _buf + dOff[p]);  \
        _Pragma("unroll")                                                      \
        for (int j = 0; j < 4; ++j) {                                          \
            float4 bx;                                                         \
            asm volatile("ld.shared.v4.b32 {%0,%1,%2,%3}, [%4];"               \
                : "=f"(bx.x), "=f"(bx.y), "=f"(bx.z), "=f"(bx.w)               \
                : "r"(SLOT(j)));                                               \
            cvt_store_f16(bx, _buf + BF_BH + dOff[j]);                         \
        }                                                                      \
    } while (0)

    // ---- mma fragment mapping (validated R6-R14)
    const int rA = (lane & 7) + (((lane >> 3) & 1) << 3);
    const int gA = (lane >> 4) & 1;
    const int rB = (lane & 7) + (((lane >> 4) & 1) << 3);
    const int gB = (lane >> 3) & 1;
    const int xA2 = (rA >> 1) & 3;
    const int xB2 = (rB >> 1) & 3;

    float acc[4][4][4];
#pragma unroll
    for (int i = 0; i < 4; ++i)
#pragma unroll
        for (int j = 0; j < 4; ++j)
#pragma unroll
            for (int k = 0; k < 4; ++k) acc[i][j][k] = 0.0f;

    // ---- prologue: chunk 0 converted into buf 0; chunk 1 in flight
    CP_B(0);
    LDG_A(0);
    CONVERT(0);
    CP_B(1);
    LDG_A(1);
    __syncthreads();

#pragma unroll 1
    for (int kt = 0; kt < 32; ++kt) {
        // mma on fp16 buf kt&1 (ready; synced). areg holds chunk kt+1.
        {
            const uint32_t bufb = sb + SM_BF + (kt & 1) * BF_BUF;
            const uint32_t AH = bufb;
            const uint32_t AL = bufb + 8192;
            const uint32_t BH = bufb + BF_BH;
#pragma unroll
            for (int k16 = 0; k16 < 2; ++k16) {
                const int cA = ((2 * k16 + gA) ^ xA2) << 4;
                const int cB = ((2 * k16 + gB) ^ xB2) << 4;
                uint32_t ah[4][4], bh[2][4];
#pragma unroll
                for (int mi = 0; mi < 4; ++mi)
                    ldsm4(ah[mi], AH + (warpM + mi * 16 + rA) * 64 + cA);
#pragma unroll
                for (int np = 0; np < 2; ++np)
                    ldsm4(bh[np], BH + (warpN + np * 16 + rB) * 64 + cB);
                // product 1: xh * wh
#pragma unroll
                for (int mi = 0; mi < 4; ++mi)
#pragma unroll
                    for (int ni = 0; ni < 4; ++ni)
                        mma16816(acc[mi][ni], ah[mi],
                                 bh[ni >> 1][(ni & 1) * 2], bh[ni >> 1][(ni & 1) * 2 + 1]);
                // product 2: xl * wh (al reuses ah's registers)
                uint32_t al[4][4];
#pragma unroll
                for (int mi = 0; mi < 4; ++mi)
                    ldsm4(al[mi], AL + (warpM + mi * 16 + rA) * 64 + cA);
#pragma unroll
                for (int mi = 0; mi < 4; ++mi)
#pragma unroll
                    for (int ni = 0; ni < 4; ++ni)
                        mma16816(acc[mi][ni], al[mi],
                                 bh[ni >> 1][(ni & 1) * 2], bh[ni >> 1][(ni & 1) * 2 + 1]);
            }
        }

        // convert chunk kt+1 into buf (kt+1)&1, then start chunk kt+2 loads
        if (kt + 1 < 32) CONVERT((kt + 1) & 1);
        if (kt + 2 < 32) {
            CP_B(kt + 2);
            LDG_A(kt + 2);
        }
        __syncthreads();
    }

    // ---- epilogue: tanh(acc + bias2)*v, reduce over n, atomicAdd scores ----
    const float* sbias = (const float*)(smem + SM_BIAS);
    const float* sv    = (const float*)(smem + SM_V);
    const int q = lane & 3;
    const int r = lane >> 2;

#pragma unroll
    for (int mi = 0; mi < 4; ++mi) {
        float pa = 0.0f, pb = 0.0f;
#pragma unroll
        for (int ni = 0; ni < 4; ++ni) {
            const int n0 = warpN + ni * 8 + 2 * q;
            const float b0 = sbias[n0], b1 = sbias[n0 + 1];
            const float v0 = sv[n0],    v1 = sv[n0 + 1];
            pa += fast_tanh(acc[mi][ni][0] + b0) * v0 +
                  fast_tanh(acc[mi][ni][1] + b1) * v1;
            pb += fast_tanh(acc[mi][ni][2] + b0) * v0 +
                  fast_tanh(acc[mi][ni][3] + b1) * v1;
        }
        pa += __shfl_xor_sync(0xffffffffu, pa, 1);
        pa += __shfl_xor_sync(0xffffffffu, pa, 2);
        pb += __shfl_xor_sync(0xffffffffu, pb, 1);
        pb += __shfl_xor_sync(0xffffffffu, pb, 2);
        if (q == 0) {
            const int m = rowBase + warpM + mi * 16 + r;
            atomicAdd(&g_scores[m], pa);
            atomicAdd(&g_scores[m + 8], pb);
        }
    }
}

// ---------------- kernel 3: softmax over S per batch ------------------------
__global__ void softmax_kernel(float* __restrict__ attn) {
    __shared__ float red[8];
    const int b = blockIdx.x, t = threadIdx.x;
    const float* s = g_scores + b * S_;

    float loc[8];
    float mx = -1e30f;
#pragma unroll
    for (int i = 0; i < 8; ++i) {
        loc[i] = s[t + i * 256];
        mx = fmaxf(mx, loc[i]);
    }
#pragma unroll
    for (int off = 16; off; off >>= 1)
        mx = fmaxf(mx, __shfl_xor_sync(0xffffffffu, mx, off));
    if ((t & 31) == 0) red[t >> 5] = mx;
    __syncthreads();
    float bm = red[0];
#pragma unroll
    for (int w = 1; w < 8; ++w) bm = fmaxf(bm, red[w]);
    __syncthreads();

    float sum = 0.0f;
#pragma unroll
    for (int i = 0; i < 8; ++i) {
        loc[i] = expf(loc[i] - bm);
        sum += loc[i];
    }
#pragma unroll
    for (int off = 16; off; off >>= 1)
        sum += __shfl_xor_sync(0xffffffffu, sum, off);
    if ((t & 31) == 0) red[t >> 5] = sum;
    __syncthreads();
    float bs = 0.0f;
#pragma unroll
    for (int w = 0; w < 8; ++w) bs += red[w];

    const float inv = 1.0f / bs;
#pragma unroll
    for (int i = 0; i < 8; ++i)
        attn[b * S_ + t + i * 256] = loc[i] * inv;
}

// ---------------- kernel 4: context = attn @ enc ----------------------------
__global__ void context_kernel(const float* __restrict__ enc,
                               const float* __restrict__ attn,
                               float* __restrict__ ctx) {
    __shared__ float ws[128];
    const int b  = blockIdx.x;
    const int s0 = blockIdx.y * 128;
    if (threadIdx.x < 128) ws[threadIdx.x] = attn[b * S_ + s0 + threadIdx.x];
    __syncthreads();

    const int h = threadIdx.x * 4;
    float4 acc = make_float4(0.f, 0.f, 0.f, 0.f);
    const float* base = enc + ((size_t)b * S_ + s0) * H_ + h;
#pragma unroll 4
    for (int s = 0; s < 128; ++s) {
        const float w = ws[s];
        float4 e = *(const float4*)(base + (size_t)s * H_);
        acc.x += w * e.x;  acc.y += w * e.y;
        acc.z += w * e.z;  acc.w += w * e.w;
    }
    atomicAdd(&ctx[b * H_ + h + 0], acc.x);
    atomicAdd(&ctx[b * H_ + h + 1], acc.y);
    atomicAdd(&ctx[b * H_ + h + 2], acc.z);
    atomicAdd(&ctx[b * H_ + h + 3], acc.w);
}

// ---------------- launch ----------------------------------------------------
extern "C" void kernel_launch(void* const* d_in, const int* in_sizes, int n_in,
                              void* d_out, int out_size) {
    const float* hidden = (const float*)d_in[0];   // [B,H]
    const float* enc    = (const float*)d_in[1];   // [B,S,H]
    const float* W      = (const float*)d_in[2];   // [H,H]
    const float* b_attn = (const float*)d_in[3];   // [H]
    const float* v      = (const float*)d_in[4];   // [H]

    float* out  = (float*)d_out;
    float* ctx  = out;             // [B,H]
    float* attn = out + B_ * H_;   // [B,S]

    // idempotent, executed every call (no static guards)
    cudaFuncSetAttribute((const void*)energy_mma,
                         cudaFuncAttributeMaxDynamicSharedMemorySize, SM_TOTAL);

    zero_kernel<<<256, 256>>>(ctx);
    bias2_kernel<<<dim3(B_, H_ / 8), 256>>>(hidden, W, b_attn);
    energy_mma<<<dim3(H_ / 128, BS_ / 128), 256, SM_TOTAL>>>(enc, W, v);
    softmax_kernel<<<B_, 256>>>(attn);
    context_kernel<<<dim3(B_, 16), 256>>>(enc, attn, ctx);
}